// round 1
// baseline (speedup 1.0000x reference)
#include <cuda_runtime.h>
#include <math.h>

// ---------------------------------------------------------------------------
// BertSelfAttention: B=4, S=2048, D=1024, H=16, d=64
//   q = x @ Wq^T + bq ; k = ... ; v = ...   (3x GEMM 8192x1024x1024)
//   scores = q k^T / 8 + mask ; probs = softmax ; ctx = probs v
//   out[b,s,h*64+c]
// Round 0: fp32 baseline. SGEMM 128x128x8 + flash-attention Br=Bc=64.
// ---------------------------------------------------------------------------

#define B_ 4
#define S_ 2048
#define D_ 1024
#define H_ 16
#define HD_ 64

// Scratch: Q,K,V in [B,H,S,64] layout (32 MB each). Device globals = allowed.
__device__ float g_q[(size_t)B_ * H_ * S_ * HD_];
__device__ float g_k[(size_t)B_ * H_ * S_ * HD_];
__device__ float g_v[(size_t)B_ * H_ * S_ * HD_];

// ---------------------------------------------------------------------------
// QKV GEMM: C[m,n] = sum_k X[m,k] * W[n,k] + bias[n]
// Block tile 128x128, k-chunk 8, 256 threads, 8x8 per thread (split-4 layout).
// Output scattered to [B,H,S,64].
// ---------------------------------------------------------------------------
__global__ __launch_bounds__(256) void qkv_gemm(
    const float* __restrict__ X,
    const float* __restrict__ Wq, const float* __restrict__ bq,
    const float* __restrict__ Wk, const float* __restrict__ bk,
    const float* __restrict__ Wv, const float* __restrict__ bv)
{
    const float* W;
    const float* bias;
    float* Out;
    if (blockIdx.z == 0)      { W = Wq; bias = bq; Out = g_q; }
    else if (blockIdx.z == 1) { W = Wk; bias = bk; Out = g_k; }
    else                      { W = Wv; bias = bv; Out = g_v; }

    __shared__ float As[8][128];   // As[k][m]
    __shared__ float Bs[8][128];   // Bs[k][n]

    const int m0 = blockIdx.x * 128;
    const int n0 = blockIdx.y * 128;
    const int tid = threadIdx.x;
    const int ty = tid >> 4;        // 0..15
    const int tx = tid & 15;        // 0..15
    const int lrow = tid >> 1;      // 0..127
    const int lk   = (tid & 1) * 4; // 0 or 4

    float acc[8][8];
    #pragma unroll
    for (int i = 0; i < 8; i++)
        #pragma unroll
        for (int j = 0; j < 8; j++) acc[i][j] = 0.f;

    const float* xg = X + (size_t)(m0 + lrow) * D_ + lk;
    const float* wg = W + (size_t)(n0 + lrow) * D_ + lk;

    for (int k0 = 0; k0 < D_; k0 += 8) {
        float4 xa = *(const float4*)(xg + k0);
        float4 wa = *(const float4*)(wg + k0);
        As[lk + 0][lrow] = xa.x;
        As[lk + 1][lrow] = xa.y;
        As[lk + 2][lrow] = xa.z;
        As[lk + 3][lrow] = xa.w;
        Bs[lk + 0][lrow] = wa.x;
        Bs[lk + 1][lrow] = wa.y;
        Bs[lk + 2][lrow] = wa.z;
        Bs[lk + 3][lrow] = wa.w;
        __syncthreads();

        #pragma unroll
        for (int kk = 0; kk < 8; kk++) {
            float4 a0 = *(const float4*)&As[kk][ty * 4];
            float4 a1 = *(const float4*)&As[kk][64 + ty * 4];
            float4 b0 = *(const float4*)&Bs[kk][tx * 4];
            float4 b1 = *(const float4*)&Bs[kk][64 + tx * 4];
            float ar[8] = {a0.x, a0.y, a0.z, a0.w, a1.x, a1.y, a1.z, a1.w};
            float br[8] = {b0.x, b0.y, b0.z, b0.w, b1.x, b1.y, b1.z, b1.w};
            #pragma unroll
            for (int i = 0; i < 8; i++)
                #pragma unroll
                for (int j = 0; j < 8; j++)
                    acc[i][j] += ar[i] * br[j];
        }
        __syncthreads();
    }

    // Epilogue: scatter to [B,H,S,64] with bias.
    #pragma unroll
    for (int i = 0; i < 8; i++) {
        int mloc = (i < 4) ? (ty * 4 + i) : (64 + ty * 4 + i - 4);
        int m = m0 + mloc;
        int b = m >> 11;        // /2048
        int s = m & 2047;
        #pragma unroll
        for (int j = 0; j < 8; j++) {
            int nloc = (j < 4) ? (tx * 4 + j) : (64 + tx * 4 + j - 4);
            int n = n0 + nloc;
            int h = n >> 6;
            int c = n & 63;
            Out[(((size_t)(b * H_ + h)) * S_ + s) * HD_ + c] = acc[i][j] + bias[n];
        }
    }
}

// ---------------------------------------------------------------------------
// Flash attention: grid = (S/64, B*H), 256 threads (16x16), 4x4 per thread.
// Br = Bc = 64, d = 64. Online softmax with width-16 shuffles.
// ---------------------------------------------------------------------------
#define PAD 68

__global__ __launch_bounds__(256) void flash_attn(
    const float* __restrict__ mask, float* __restrict__ out)
{
    extern __shared__ float sm[];
    float* Qt  = sm;                 // [64][PAD]  Qt[k*PAD + r]   (transposed)
    float* Kt  = Qt + 64 * PAD;      // [64][PAD]  Kt[k*PAD + c]   (transposed)
    float* Vs  = Kt + 64 * PAD;      // [64][PAD]  Vs[k*PAD + c]   (natural)
    float* Ps  = Vs + 64 * PAD;      // [64][PAD]  Ps[r*PAD + c]
    float* msk = Ps + 64 * PAD;      // [64]

    const int bh = blockIdx.y;       // b*16 + h
    const int b  = bh >> 4;
    const int h  = bh & 15;
    const int q0 = blockIdx.x * 64;
    const int tid = threadIdx.x;
    const int ty = tid >> 4;
    const int tx = tid & 15;

    const float* Qg = g_q + ((size_t)bh * S_ + q0) * HD_;
    const float* Kg = g_k + (size_t)bh * S_ * HD_;
    const float* Vg = g_v + (size_t)bh * S_ * HD_;
    const float* mg = mask + (size_t)b * S_;

    // Load Q tile, transposed into smem.
    #pragma unroll
    for (int i = 0; i < 4; i++) {
        int f = tid + i * 256;        // 0..1023 float4 slots
        int r = f >> 4;               // 0..63
        int c = (f & 15) * 4;         // 0..60
        float4 q4 = *(const float4*)(Qg + r * HD_ + c);
        Qt[(c + 0) * PAD + r] = q4.x;
        Qt[(c + 1) * PAD + r] = q4.y;
        Qt[(c + 2) * PAD + r] = q4.z;
        Qt[(c + 3) * PAD + r] = q4.w;
    }

    float o[4][4];
    float m_i[4], l_i[4];
    #pragma unroll
    for (int i = 0; i < 4; i++) {
        m_i[i] = -INFINITY;
        l_i[i] = 0.f;
        #pragma unroll
        for (int j = 0; j < 4; j++) o[i][j] = 0.f;
    }

    for (int kv = 0; kv < S_; kv += 64) {
        // Load K (transposed) + V (natural) tiles.
        #pragma unroll
        for (int i = 0; i < 4; i++) {
            int f = tid + i * 256;
            int r = f >> 4;
            int c = (f & 15) * 4;
            float4 k4 = *(const float4*)(Kg + (size_t)(kv + r) * HD_ + c);
            Kt[(c + 0) * PAD + r] = k4.x;
            Kt[(c + 1) * PAD + r] = k4.y;
            Kt[(c + 2) * PAD + r] = k4.z;
            Kt[(c + 3) * PAD + r] = k4.w;
            float4 v4 = *(const float4*)(Vg + (size_t)(kv + r) * HD_ + c);
            *(float4*)(Vs + r * PAD + c) = v4;
        }
        if (tid < 64) msk[tid] = mg[kv + tid];
        __syncthreads();

        // S = Q K^T  (4x4 per thread, k over 64)
        float s[4][4];
        #pragma unroll
        for (int i = 0; i < 4; i++)
            #pragma unroll
            for (int j = 0; j < 4; j++) s[i][j] = 0.f;

        #pragma unroll
        for (int k = 0; k < 64; k++) {
            float4 a = *(const float4*)(Qt + k * PAD + ty * 4);
            float4 bb = *(const float4*)(Kt + k * PAD + tx * 4);
            float ar[4] = {a.x, a.y, a.z, a.w};
            float br[4] = {bb.x, bb.y, bb.z, bb.w};
            #pragma unroll
            for (int i = 0; i < 4; i++)
                #pragma unroll
                for (int j = 0; j < 4; j++)
                    s[i][j] += ar[i] * br[j];
        }

        // Online softmax per row (rows of same ty live on a 16-lane group).
        #pragma unroll
        for (int i = 0; i < 4; i++) {
            float rmax = -INFINITY;
            #pragma unroll
            for (int j = 0; j < 4; j++) {
                s[i][j] = s[i][j] * 0.125f + msk[tx * 4 + j];
                rmax = fmaxf(rmax, s[i][j]);
            }
            #pragma unroll
            for (int off = 8; off >= 1; off >>= 1)
                rmax = fmaxf(rmax, __shfl_xor_sync(0xffffffffu, rmax, off, 16));

            float mnew = fmaxf(m_i[i], rmax);
            float alpha = __expf(m_i[i] - mnew);
            float rsum = 0.f;
            #pragma unroll
            for (int j = 0; j < 4; j++) {
                float p = __expf(s[i][j] - mnew);
                s[i][j] = p;
                rsum += p;
            }
            #pragma unroll
            for (int off = 8; off >= 1; off >>= 1)
                rsum += __shfl_xor_sync(0xffffffffu, rsum, off, 16);

            l_i[i] = l_i[i] * alpha + rsum;
            m_i[i] = mnew;
            #pragma unroll
            for (int j = 0; j < 4; j++) o[i][j] *= alpha;

            *(float4*)(Ps + (ty * 4 + i) * PAD + tx * 4) =
                make_float4(s[i][0], s[i][1], s[i][2], s[i][3]);
        }
        __syncthreads();

        // O += P V
        #pragma unroll
        for (int k = 0; k < 64; k++) {
            float4 v = *(const float4*)(Vs + k * PAD + tx * 4);
            #pragma unroll
            for (int i = 0; i < 4; i++) {
                float p = Ps[(ty * 4 + i) * PAD + k];
                o[i][0] += p * v.x;
                o[i][1] += p * v.y;
                o[i][2] += p * v.z;
                o[i][3] += p * v.w;
            }
        }
        __syncthreads();
    }

    // Normalize and write out[b, s, h*64 + c].
    #pragma unroll
    for (int i = 0; i < 4; i++) {
        float inv = 1.f / l_i[i];
        int srow = q0 + ty * 4 + i;
        float4 r4 = make_float4(o[i][0] * inv, o[i][1] * inv,
                                o[i][2] * inv, o[i][3] * inv);
        *(float4*)(out + ((size_t)(b * S_ + srow)) * D_ + h * HD_ + tx * 4) = r4;
    }
}

// ---------------------------------------------------------------------------
extern "C" void kernel_launch(void* const* d_in, const int* in_sizes, int n_in,
                              void* d_out, int out_size)
{
    const float* hidden = (const float*)d_in[0];
    const float* mask   = (const float*)d_in[1];
    const float* qw     = (const float*)d_in[2];
    const float* qb     = (const float*)d_in[3];
    const float* kw     = (const float*)d_in[4];
    const float* kb     = (const float*)d_in[5];
    const float* vw     = (const float*)d_in[6];
    const float* vb     = (const float*)d_in[7];
    float* out = (float*)d_out;

    dim3 g1(8192 / 128, 1024 / 128, 3);
    qkv_gemm<<<g1, 256>>>(hidden, qw, qb, kw, kb, vw, vb);

    const int smem_bytes = (4 * 64 * PAD + 64) * (int)sizeof(float);
    cudaFuncSetAttribute(flash_attn,
                         cudaFuncAttributeMaxDynamicSharedMemorySize, smem_bytes);
    dim3 g2(S_ / 64, B_ * H_);
    flash_attn<<<g2, 256, smem_bytes>>>(mask, out);
}